// round 15
// baseline (speedup 1.0000x reference)
#include <cuda_runtime.h>

// TwoCompartmentLIF: T=50, N=500000.
// R4:  196.7us float4/thr, 86r, occ 21%, DRAM 57%
// R6:  168.1us float2/thr, 48r, occ 48%, DRAM 66.5%
// R10: 151.7us scalar/thr, 32r, occ 81%, DRAM 72.6%, issue 61%
//   -> occupancy saturated; residual = cross-iteration load exposure (regs too
//      tight to keep t+1 loads in flight during t compute).
// R11: 2-stage software pipeline: prefetch t+1's 7 inputs before computing t.
//      launch_bounds(256,6) -> <=42 regs, 6 blocks/SM (75% occ), MLP ~2x.

#define T_STEPS 50
#define N_NEUR  500000

#define G_L      0.05f
#define E_L      0.0f
#define G_L_D    0.03f
#define INV_C_D  2.0f
#define G_C      0.05f
#define E_E      3.0f
#define E_I      (-0.5f)
#define E_NMDA   3.0f
#define E_GABA_B (-0.8f)
#define E_CA     4.0f
#define V_TH     1.0f
#define V_RESET  0.0f
#define TAU_REF  5.0f
#define DT       1.0f
#define MG_K     5.0f
#define MG_VHALF 0.5f
#define THETA_CA 2.0f
#define G_CA_SPIKE 0.3f
#define BAP_AMP  0.3f
#define D_E   0.81873075307798185867f
#define D_I   0.90483741803595957316f
#define D_N   0.99004983374916805357f
#define D_GB  0.99750312239746142239f
#define D_CA  0.95122942450071400910f
// gAd identically zero (ADAPT_INC == 0) -> elided.

__device__ __forceinline__ float sigmoidf_(float x) {
    return 1.0f / (1.0f + expf(-x));
}

__global__ __launch_bounds__(256, 6)
void lif_kernel(const float* __restrict__ inEb, const float* __restrict__ inIb,
                const float* __restrict__ inNb, const float* __restrict__ inGB,
                const float* __restrict__ inEa, const float* __restrict__ inIa,
                const float* __restrict__ inNa,
                float* __restrict__ out_spk, float* __restrict__ out_v)
{
    const int i = blockIdx.x * blockDim.x + threadIdx.x;
    if (i >= N_NEUR) return;

    float vs  = 0.f, vd  = 0.f;
    float gEb = 0.f, gIb = 0.f, gNb = 0.f, gGB = 0.f;
    float gEa = 0.f, gIa = 0.f, gNa = 0.f, gCa = 0.f;
    float ref = 0.f;

    // prologue: load t=0
    int off = i;
    float cEb = __ldcs(inEb + off);
    float cIb = __ldcs(inIb + off);
    float cNb = __ldcs(inNb + off);
    float cGB = __ldcs(inGB + off);
    float cEa = __ldcs(inEa + off);
    float cIa = __ldcs(inIa + off);
    float cNa = __ldcs(inNa + off);

    #pragma unroll 2
    for (int t = 0; t < T_STEPS; ++t) {
        // prefetch t+1 BEFORE computing t (keeps next loads in flight
        // while this iteration's FMA chain executes)
        float nEb, nIb, nNb, nGB, nEa, nIa, nNa;
        if (t + 1 < T_STEPS) {
            const int noff = off + N_NEUR;
            nEb = __ldcs(inEb + noff);
            nIb = __ldcs(inIb + noff);
            nNb = __ldcs(inNb + noff);
            nGB = __ldcs(inGB + noff);
            nEa = __ldcs(inEa + noff);
            nIa = __ldcs(inIa + noff);
            nNa = __ldcs(inNa + noff);
        }

        gEb = gEb * D_E  + cEb;
        gIb = gIb * D_I  + cIb;
        gNb = gNb * D_N  + cNb;
        gGB = gGB * D_GB + cGB;
        gEa = gEa * D_E  + cEa;
        gIa = gIa * D_I  + cIa;
        gNa = gNa * D_N  + cNa;
        gCa = gCa * D_CA;

        const float mg_s = sigmoidf_(MG_K * (vs - MG_VHALF));
        const float mg_d = sigmoidf_(MG_K * (vd - MG_VHALF));

        float I_s = G_L * (E_L - vs)
                  + gEb * (E_E - vs)
                  + gIb * (E_I - vs)
                  + gNb * mg_s * (E_NMDA - vs)
                  + gGB * (E_GABA_B - vs)
                  + G_C * (vd - vs);

        float I_d = G_L_D * (E_L - vd)
                  + gEa * (E_E - vd)
                  + gIa * (E_I - vd)
                  + gNa * mg_d * (E_NMDA - vd)
                  + gCa * (E_CA - vd)
                  + G_C * (vs - vd);

        const bool refractory = ref > 0.0f;
        float v_s_new = refractory ? V_RESET : (vs + DT * I_s);
        float v_d_new = vd + INV_C_D * I_d;

        const bool spike = (v_s_new >= V_TH) && !refractory;
        const float spike_f = spike ? 1.0f : 0.0f;

        v_s_new = spike ? V_RESET : v_s_new;
        ref     = spike ? TAU_REF : fmaxf(ref - DT, 0.0f);
        v_d_new = spike ? (v_d_new + BAP_AMP * (E_CA - v_d_new)) : v_d_new;
        gCa    += (v_d_new >= THETA_CA) ? G_CA_SPIKE : 0.0f;

        vs = v_s_new;
        vd = v_d_new;

        __stcs(out_spk + off, spike_f);
        __stcs(out_v   + off, v_s_new);

        // rotate buffers
        cEb = nEb; cIb = nIb; cNb = nNb; cGB = nGB;
        cEa = nEa; cIa = nIa; cNa = nNa;
        off += N_NEUR;
    }
}

extern "C" void kernel_launch(void* const* d_in, const int* in_sizes, int n_in,
                              void* d_out, int out_size)
{
    const float* inEb = (const float*)d_in[0];
    const float* inIb = (const float*)d_in[1];
    const float* inNb = (const float*)d_in[2];
    const float* inGB = (const float*)d_in[3];
    const float* inEa = (const float*)d_in[4];
    const float* inIa = (const float*)d_in[5];
    const float* inNa = (const float*)d_in[6];

    float* out = (float*)d_out;
    float* out_spk = out;                                   // [T, N]
    float* out_v   = out + (size_t)T_STEPS * N_NEUR;        // [T, N]

    const int threads = 256;
    const int blocks  = (N_NEUR + threads - 1) / threads;   // 1954
    lif_kernel<<<blocks, threads>>>(inEb, inIb, inNb, inGB, inEa, inIa, inNa,
                                    out_spk, out_v);
}

// round 16
// speedup vs baseline: 1.2717x; 1.2717x over previous
#include <cuda_runtime.h>

// TwoCompartmentLIF: T=50, N=500000.
// R10: 151.7us scalar/thr, 32r (regfile 100% full), occ 81%, DRAM 72.6%
// R15: 258.0us pipeline + launch_bounds(256,6): reg cap forced SPILLS
//      (L1 25->46%, DRAM 43%) + predicated prefetch. FAILED.
// R16: pipeline, NO reg cap (natural ~46-48r, 5 blocks/SM), NO branch
//      (clamped prefetch offset -> unconditional load batch).
//      40 warps x MLP 14 = 1.54x outstanding loads vs R10.

#define T_STEPS 50
#define N_NEUR  500000

#define G_L      0.05f
#define E_L      0.0f
#define G_L_D    0.03f
#define INV_C_D  2.0f
#define G_C      0.05f
#define E_E      3.0f
#define E_I      (-0.5f)
#define E_NMDA   3.0f
#define E_GABA_B (-0.8f)
#define E_CA     4.0f
#define V_TH     1.0f
#define V_RESET  0.0f
#define TAU_REF  5.0f
#define DT       1.0f
#define MG_K     5.0f
#define MG_VHALF 0.5f
#define THETA_CA 2.0f
#define G_CA_SPIKE 0.3f
#define BAP_AMP  0.3f
#define D_E   0.81873075307798185867f
#define D_I   0.90483741803595957316f
#define D_N   0.99004983374916805357f
#define D_GB  0.99750312239746142239f
#define D_CA  0.95122942450071400910f
// gAd identically zero (ADAPT_INC == 0) -> elided.

__device__ __forceinline__ float sigmoidf_(float x) {
    return 1.0f / (1.0f + expf(-x));
}

__global__ __launch_bounds__(256)
void lif_kernel(const float* __restrict__ inEb, const float* __restrict__ inIb,
                const float* __restrict__ inNb, const float* __restrict__ inGB,
                const float* __restrict__ inEa, const float* __restrict__ inIa,
                const float* __restrict__ inNa,
                float* __restrict__ out_spk, float* __restrict__ out_v)
{
    const int i = blockIdx.x * blockDim.x + threadIdx.x;
    if (i >= N_NEUR) return;

    float vs  = 0.f, vd  = 0.f;
    float gEb = 0.f, gIb = 0.f, gNb = 0.f, gGB = 0.f;
    float gEa = 0.f, gIa = 0.f, gNa = 0.f, gCa = 0.f;
    float ref = 0.f;

    // prologue: load t=0
    int off = i;
    float cEb = __ldcs(inEb + off);
    float cIb = __ldcs(inIb + off);
    float cNb = __ldcs(inNb + off);
    float cGB = __ldcs(inGB + off);
    float cEa = __ldcs(inEa + off);
    float cIa = __ldcs(inIa + off);
    float cNa = __ldcs(inNa + off);

    for (int t = 0; t < T_STEPS; ++t) {
        // UNCONDITIONAL prefetch of t+1 (clamped: last iter re-loads itself,
        // negligible cost, keeps the 7-load batch branch-free and hoistable)
        const int tn = (t + 1 < T_STEPS) ? (t + 1) : t;   // compiles to min, no branch
        const int noff = tn * N_NEUR + i;
        const float nEb = __ldcs(inEb + noff);
        const float nIb = __ldcs(inIb + noff);
        const float nNb = __ldcs(inNb + noff);
        const float nGB = __ldcs(inGB + noff);
        const float nEa = __ldcs(inEa + noff);
        const float nIa = __ldcs(inIa + noff);
        const float nNa = __ldcs(inNa + noff);

        gEb = gEb * D_E  + cEb;
        gIb = gIb * D_I  + cIb;
        gNb = gNb * D_N  + cNb;
        gGB = gGB * D_GB + cGB;
        gEa = gEa * D_E  + cEa;
        gIa = gIa * D_I  + cIa;
        gNa = gNa * D_N  + cNa;
        gCa = gCa * D_CA;

        const float mg_s = sigmoidf_(MG_K * (vs - MG_VHALF));
        const float mg_d = sigmoidf_(MG_K * (vd - MG_VHALF));

        float I_s = G_L * (E_L - vs)
                  + gEb * (E_E - vs)
                  + gIb * (E_I - vs)
                  + gNb * mg_s * (E_NMDA - vs)
                  + gGB * (E_GABA_B - vs)
                  + G_C * (vd - vs);

        float I_d = G_L_D * (E_L - vd)
                  + gEa * (E_E - vd)
                  + gIa * (E_I - vd)
                  + gNa * mg_d * (E_NMDA - vd)
                  + gCa * (E_CA - vd)
                  + G_C * (vs - vd);

        const bool refractory = ref > 0.0f;
        float v_s_new = refractory ? V_RESET : (vs + DT * I_s);
        float v_d_new = vd + INV_C_D * I_d;

        const bool spike = (v_s_new >= V_TH) && !refractory;
        const float spike_f = spike ? 1.0f : 0.0f;

        v_s_new = spike ? V_RESET : v_s_new;
        ref     = spike ? TAU_REF : fmaxf(ref - DT, 0.0f);
        v_d_new = spike ? (v_d_new + BAP_AMP * (E_CA - v_d_new)) : v_d_new;
        gCa    += (v_d_new >= THETA_CA) ? G_CA_SPIKE : 0.0f;

        vs = v_s_new;
        vd = v_d_new;

        __stcs(out_spk + off, spike_f);
        __stcs(out_v   + off, v_s_new);

        // rotate buffers
        cEb = nEb; cIb = nIb; cNb = nNb; cGB = nGB;
        cEa = nEa; cIa = nIa; cNa = nNa;
        off += N_NEUR;
    }
}

extern "C" void kernel_launch(void* const* d_in, const int* in_sizes, int n_in,
                              void* d_out, int out_size)
{
    const float* inEb = (const float*)d_in[0];
    const float* inIb = (const float*)d_in[1];
    const float* inNb = (const float*)d_in[2];
    const float* inGB = (const float*)d_in[3];
    const float* inEa = (const float*)d_in[4];
    const float* inIa = (const float*)d_in[5];
    const float* inNa = (const float*)d_in[6];

    float* out = (float*)d_out;
    float* out_spk = out;                                   // [T, N]
    float* out_v   = out + (size_t)T_STEPS * N_NEUR;        // [T, N]

    const int threads = 256;
    const int blocks  = (N_NEUR + threads - 1) / threads;   // 1954
    lif_kernel<<<blocks, threads>>>(inEb, inIb, inNb, inGB, inEa, inIa, inNa,
                                    out_spk, out_v);
}